// round 3
// baseline (speedup 1.0000x reference)
#include <cuda_runtime.h>

#define NN 100000
#define EE 200000
#define KK 16
#define FF 32
#define EPS 1e-5f

// Scratch (static device globals — no allocation).
__device__ float g_pmpd[NN * FF];   // segment_sum(y, dst) -> [N, F]
__device__ float g_stats[128];      // [xsum32 | xssq32 | ysum32 | yssq32]

// ---------------------------------------------------------------------------
__global__ void k_zero() {
    int i = blockIdx.x * 256 + threadIdx.x;
    if (i < NN * FF) g_pmpd[i] = 0.f;
    if (i < 128) g_stats[i] = 0.f;
}

// segment_sum: one warp per edge, lane = feature. 6.4M REDG fp32.
__global__ void k_scatter(const float* __restrict__ y, const int* __restrict__ dst) {
    int i = blockIdx.x * 256 + threadIdx.x;   // i in [0, EE*FF), exact
    int e = i >> 5, f = i & 31;
    int d = __ldg(&dst[e]);                    // broadcast within warp
    atomicAdd(&g_pmpd[d * FF + f], y[i]);
}

// ---------------------------------------------------------------------------
// Main fused kernel: per row r (node or edge):
//   z = [v, deg*v, sum_k feat[t[r,k]], sum_k feat[tt[r,k]], p]   (160 floats)
//   out = z @ Wbig + bias_total ; relu on cols [16:32) ; accumulate BN stats.
// Block = 256 threads = 8 warps = 16 rows. Warp handles 2 rows:
//   gather phase: full warp per row (lane = feature, coalesced 128B gathers)
//   gemm phase:   half-warp per row, lane o owns output pair (o, o+16) via
//                 packed fma.rn.f32x2.
// ---------------------------------------------------------------------------
__global__ __launch_bounds__(256) void k_main(
    const float* __restrict__ feat, const float* __restrict__ deg,
    const int* __restrict__ t, const int* __restrict__ tt,
    const float* __restrict__ psrc, const int* __restrict__ pidx,
    const float* __restrict__ w0, const float* __restrict__ w1,
    const float* __restrict__ w2, const float* __restrict__ w3,
    const float* __restrict__ w4,
    const float* __restrict__ b0, const float* __restrict__ b1,
    const float* __restrict__ b2, const float* __restrict__ b3,
    const float* __restrict__ b4,
    float* __restrict__ outp, int statoff)
{
    __shared__ float2 Wpk[160][16];   // Wpk[j][o] = {Wbig[j][o], Wbig[j][o+16]}
    __shared__ float2 zsh[16][160];   // duplicated {v,v} per entry
    __shared__ float biastot[32];
    __shared__ float s_sum[32], s_ssq[32];

    const float* pbase = psrc ? psrc : g_pmpd;
    float* stats = g_stats + statoff;

    int tid = threadIdx.x;
    // Stage packed weights.
    for (int i = tid; i < 160 * 16; i += 256) {
        int j = i >> 4, o = i & 15;
        const float* src = (j < 32) ? w0 : (j < 64) ? w1 : (j < 96) ? w2
                                   : (j < 128) ? w3 : w4;
        int jr = j & 31;
        Wpk[j][o] = make_float2(src[jr * 32 + o], src[jr * 32 + o + 16]);
    }
    if (tid < 32) {
        biastot[tid] = b0[tid] + b1[tid] + b2[tid] + b3[tid] + b4[tid];
        s_sum[tid] = 0.f; s_ssq[tid] = 0.f;
    }
    __syncthreads();

    int lane = tid & 31, warp = tid >> 5;
    int row0 = blockIdx.x * 16;

    // ---- Gather phase: warp processes its 2 rows sequentially ----
    #pragma unroll
    for (int s = 0; s < 2; s++) {
        int m = warp * 2 + s;
        int n = row0 + m;
        float xv = feat[n * FF + lane];
        float dv = deg[n] * xv;
        int idxr = (lane < 16) ? t[n * KK + lane] : tt[n * KK + lane - 16];
        float a0 = 0.f, a1 = 0.f;
        #pragma unroll
        for (int k = 0; k < 16; k++) {
            int i0 = __shfl_sync(0xffffffffu, idxr, k);
            int i1 = __shfl_sync(0xffffffffu, idxr, k + 16);
            a0 += feat[i0 * FF + lane];
            a1 += feat[i1 * FF + lane];
        }
        float pv = pidx ? pbase[pidx[n] * FF + lane] : pbase[n * FF + lane];
        zsh[m][lane]        = make_float2(xv, xv);
        zsh[m][32 + lane]   = make_float2(dv, dv);
        zsh[m][64 + lane]   = make_float2(a0, a0);
        zsh[m][96 + lane]   = make_float2(a1, a1);
        zsh[m][128 + lane]  = make_float2(pv, pv);
    }
    __syncwarp();   // z produced & consumed within the same warp only

    // ---- GEMM phase: half-warp per row, packed f32x2 FMA ----
    int m = warp * 2 + (lane >> 4);
    int o = lane & 15;
    union { unsigned long long u; float2 f; } acc;
    acc.f = make_float2(biastot[o], biastot[o + 16]);
    const unsigned long long* zp = (const unsigned long long*)(&zsh[m][0]);
    #pragma unroll 16
    for (int j = 0; j < 160; j++) {
        unsigned long long a = zp[j];
        unsigned long long b = *(const unsigned long long*)(&Wpk[j][o]);
        asm("fma.rn.f32x2 %0, %1, %2, %0;" : "+l"(acc.u) : "l"(a), "l"(b));
    }
    float lo = acc.f.x;
    float hi = fmaxf(acc.f.y, 0.f);   // relu on cols [F/2, F)
    int row = row0 + m;
    outp[row * FF + o]      = lo;
    outp[row * FF + o + 16] = hi;

    // ---- BN stats: shuffle pre-reduce across the two half-warp rows, ----
    // ---- then one shared atomic per lane, then 64 global atomics/block ----
    float vlo = lo, vslo = lo * lo, vhi = hi, vshi = hi * hi;
    // lanes o and o+16 hold different rows but the same column pair; fold rows:
    vlo  += __shfl_xor_sync(0xffffffffu, vlo, 16);
    vslo += __shfl_xor_sync(0xffffffffu, vslo, 16);
    vhi  += __shfl_xor_sync(0xffffffffu, vhi, 16);
    vshi += __shfl_xor_sync(0xffffffffu, vshi, 16);
    if (lane < 16) {
        atomicAdd(&s_sum[o],      vlo);
        atomicAdd(&s_ssq[o],      vslo);
        atomicAdd(&s_sum[o + 16], vhi);
        atomicAdd(&s_ssq[o + 16], vshi);
    }
    __syncthreads();
    if (tid < 32) {
        atomicAdd(&stats[tid],      s_sum[tid]);
        atomicAdd(&stats[32 + tid], s_ssq[tid]);
    }
}

// ---------------------------------------------------------------------------
__global__ void k_norm(float* __restrict__ out,
                       const float* __restrict__ bnxw, const float* __restrict__ bnxb,
                       const float* __restrict__ bnyw, const float* __restrict__ bnyb)
{
    int i = blockIdx.x * 256 + threadIdx.x;
    if (i >= (NN + EE) * FF) return;
    int c = i & 31;
    bool isx = i < NN * FF;
    int base = isx ? 0 : 64;
    float cnt = isx ? (float)NN : (float)EE;
    float mean = g_stats[base + c] / cnt;
    float var  = g_stats[base + 32 + c] / cnt - mean * mean;
    float w = isx ? bnxw[c] : bnyw[c];
    float b = isx ? bnxb[c] : bnyb[c];
    out[i] = (out[i] - mean) * rsqrtf(var + EPS) * w + b;
}

// ---------------------------------------------------------------------------
extern "C" void kernel_launch(void* const* d_in, const int* in_sizes, int n_in,
                              void* d_out, int out_size)
{
    const float* x        = (const float*)d_in[0];
    const float* y        = (const float*)d_in[1];
    const float* deg_g    = (const float*)d_in[2];
    const float* deg_lg   = (const float*)d_in[3];
    const int*   t_g      = (const int*)d_in[4];
    const int*   tt_g     = (const int*)d_in[5];
    const int*   t_lg     = (const int*)d_in[6];
    const int*   tt_lg    = (const int*)d_in[7];
    const int*   dst      = (const int*)d_in[8];
    const int*   pm_pd    = (const int*)d_in[9];
    const float* theta_x_w   = (const float*)d_in[10];
    const float* theta_x_b   = (const float*)d_in[11];
    const float* theta_deg_w = (const float*)d_in[12];
    const float* theta_deg_b = (const float*)d_in[13];
    const float* theta_y_w   = (const float*)d_in[14];
    const float* theta_y_b   = (const float*)d_in[15];
    const float* gamma_y_w   = (const float*)d_in[16];
    const float* gamma_y_b   = (const float*)d_in[17];
    const float* gamma_deg_w = (const float*)d_in[18];
    const float* gamma_deg_b = (const float*)d_in[19];
    const float* gamma_x_w   = (const float*)d_in[20];
    const float* gamma_x_b   = (const float*)d_in[21];
    const float* theta_r_w   = (const float*)d_in[22];  // [2,32,32]
    const float* theta_r_b   = (const float*)d_in[23];  // [2,32]
    const float* gamma_r_w   = (const float*)d_in[24];
    const float* gamma_r_b   = (const float*)d_in[25];
    const float* bn_x_w      = (const float*)d_in[26];
    const float* bn_x_b      = (const float*)d_in[27];
    const float* bn_y_w      = (const float*)d_in[28];
    const float* bn_y_b      = (const float*)d_in[29];
    float* out = (float*)d_out;

    k_zero<<<(NN * FF + 255) / 256, 256>>>();
    k_scatter<<<EE * FF / 256, 256>>>(y, dst);

    // Node side: z = [x, deg*x, agg_t, agg_tt, pmpd_y]
    k_main<<<NN / 16, 256>>>(
        x, deg_g, t_g, tt_g, /*psrc=*/nullptr, /*pidx=*/nullptr,
        theta_x_w, theta_deg_w, theta_r_w, theta_r_w + 1024, theta_y_w,
        theta_x_b, theta_deg_b, theta_r_b, theta_r_b + 32, theta_y_b,
        out, /*statoff=*/0);

    // Edge side: z = [y, deg*y, agg_t, agg_tt, x[pm_pd]]
    k_main<<<EE / 16, 256>>>(
        y, deg_lg, t_lg, tt_lg, /*psrc=*/x, /*pidx=*/pm_pd,
        gamma_y_w, gamma_deg_w, gamma_r_w, gamma_r_w + 1024, gamma_x_w,
        gamma_y_b, gamma_deg_b, gamma_r_b, gamma_r_b + 32, gamma_x_b,
        out + NN * FF, /*statoff=*/64);

    k_norm<<<((NN + EE) * FF + 255) / 256, 256>>>(out, bn_x_w, bn_x_b, bn_y_w, bn_y_b);
}